// round 2
// baseline (speedup 1.0000x reference)
#include <cuda_runtime.h>
#include <math.h>

#define BATCH   8
#define SEQ     4096
#define DIMN    512
#define HEADS   8
#define DHEAD   64
#define WIN     128
#define NW      (SEQ / WIN)
#define NTOK    (BATCH * SEQ)
#define QKVD    (3 * DIMN)
#define FFD     (4 * DIMN)

// ---------------- scratch (static device allocations; no cudaMalloc allowed) ---
__device__ float g_h[(size_t)NTOK * DIMN];       //  64 MB : LN output (reused for ff LN)
__device__ float g_qkv[(size_t)NTOK * QKVD];     // 192 MB : qkv (q/k rewritten in-place)
__device__ float g_attn[(size_t)NTOK * DIMN];    //  64 MB : attention output
__device__ float g_x1[(size_t)NTOK * DIMN];      //  64 MB : x after attn residual
__device__ float g_ff1[(size_t)NTOK * FFD];      // 256 MB : gelu(h @ w_ff1^T)

// ---------------- LayerNorm: one block / token, 128 threads, float4 ------------
__global__ __launch_bounds__(128) void ln_kernel(const float* __restrict__ in,
                                                 const float* __restrict__ gamma,
                                                 const float* __restrict__ beta,
                                                 float* __restrict__ out)
{
    int t = blockIdx.x;
    int tid = threadIdx.x;
    const float4* row = (const float4*)(in + (size_t)t * DIMN);
    float4 v = row[tid];
    float s  = v.x + v.y + v.z + v.w;
    float ss = v.x * v.x + v.y * v.y + v.z * v.z + v.w * v.w;
#pragma unroll
    for (int o = 16; o > 0; o >>= 1) {
        s  += __shfl_xor_sync(0xffffffffu, s, o);
        ss += __shfl_xor_sync(0xffffffffu, ss, o);
    }
    __shared__ float sm[4], sm2[4];
    int w = tid >> 5, lane = tid & 31;
    if (lane == 0) { sm[w] = s; sm2[w] = ss; }
    __syncthreads();
    s  = sm[0] + sm[1] + sm[2] + sm[3];
    ss = sm2[0] + sm2[1] + sm2[2] + sm2[3];
    float mean = s * (1.0f / DIMN);
    float var  = ss * (1.0f / DIMN) - mean * mean;
    float inv  = rsqrtf(var + 1e-5f);
    float4 g = ((const float4*)gamma)[tid];
    float4 b = ((const float4*)beta)[tid];
    float4 o4;
    o4.x = (v.x - mean) * inv * g.x + b.x;
    o4.y = (v.y - mean) * inv * g.y + b.y;
    o4.z = (v.z - mean) * inv * g.z + b.z;
    o4.w = (v.w - mean) * inv * g.w + b.w;
    ((float4*)(out + (size_t)t * DIMN))[tid] = o4;
}

// -------- q/k post: l2norm * scale then rotary. warp = (token, head) -----------
// lane l owns dims l and l+32 (exactly the rotary pairing).
// Trig computed in DOUBLE precision: fast-math sincosf at |x| up to ~4095 has
// unreliable range reduction; the phase itself is rounded to fp32 first to
// match the reference's fp32 freqs = pos * inv_freq computation.
__global__ __launch_bounds__(256) void qkpost_kernel(float* __restrict__ qkv,
                                                     const float* __restrict__ qsc,
                                                     const float* __restrict__ ksc)
{
    int t = blockIdx.x;          // token 0..NTOK-1
    int n = t & (SEQ - 1);       // position within sequence
    int h = threadIdx.x >> 5;    // warp -> head
    int lane = threadIdx.x & 31;

    // inv_freq = 10000^-(2*lane/64), computed in double, rounded to fp32 (as ref)
    double invf_d = exp(-(double)(2 * lane) * (9.210340371976184 / 64.0));
    float invf = (float)invf_d;
    float ph = (float)n * invf;              // fp32 phase, matches reference
    double sd, cd;
    sincos((double)ph, &sd, &cd);            // exact trig regardless of fast-math
    float c = (float)cd, s = (float)sd;

    float* base = qkv + (size_t)t * QKVD + h * DHEAD;   // q
    {
        float a = base[lane], b = base[lane + 32];
        float ssq = a * a + b * b;
#pragma unroll
        for (int o = 16; o > 0; o >>= 1) ssq += __shfl_xor_sync(0xffffffffu, ssq, o);
        float inv = 1.0f / fmaxf(sqrtf(ssq), 1e-12f);
        float an = a * inv * qsc[lane];
        float bn = b * inv * qsc[lane + 32];
        base[lane]      = an * c - bn * s;
        base[lane + 32] = bn * c + an * s;
    }
    {
        float* kb = base + DIMN;                         // k
        float a = kb[lane], b = kb[lane + 32];
        float ssq = a * a + b * b;
#pragma unroll
        for (int o = 16; o > 0; o >>= 1) ssq += __shfl_xor_sync(0xffffffffu, ssq, o);
        float inv = 1.0f / fmaxf(sqrtf(ssq), 1e-12f);
        float an = a * inv * ksc[lane];
        float bn = b * inv * ksc[lane + 32];
        kb[lane]      = an * c - bn * s;
        kb[lane + 32] = bn * c + an * s;
    }
}

// -------- local-window attention: CTA = (window, head, batch), thread = q row --
// K,V processed in 4 chunks of 64 keys (static 32 KB smem, no opt-in needed).
// Chunks 0,1 = previous window (all causal-valid for w>0, fully masked for w==0,
// skipped uniformly). Chunks 2,3 = current window with per-thread causal bound.
// Skipping masked keys is exact: reference's exp(-1e9 - max) == 0 in fp32.
__global__ __launch_bounds__(128) void attn_kernel(const float* __restrict__ qkv,
                                                   float* __restrict__ attn_out)
{
    __shared__ float sK[64][DHEAD];
    __shared__ float sV[64][DHEAD];

    int w = blockIdx.x, h = blockIdx.y, b = blockIdx.z;
    int i = threadIdx.x;
    int tok0 = b * SEQ + w * WIN;
    int tok  = tok0 + i;

    float q[DHEAD];
    {
        const float4* srcQ = (const float4*)(qkv + (size_t)tok * QKVD + h * DHEAD);
#pragma unroll
        for (int d4 = 0; d4 < 16; ++d4) {
            float4 t4 = srcQ[d4];
            q[d4 * 4 + 0] = t4.x; q[d4 * 4 + 1] = t4.y;
            q[d4 * 4 + 2] = t4.z; q[d4 * 4 + 3] = t4.w;
        }
    }

    float acc[DHEAD];
#pragma unroll
    for (int d = 0; d < DHEAD; ++d) acc[d] = 0.f;
    float m = -1e30f, l = 0.f;

#pragma unroll 1
    for (int c = 0; c < 4; ++c) {
        if (c < 2 && w == 0) continue;   // uniform across block: no sync divergence

        __syncthreads();                 // previous chunk fully consumed
        {
            int r  = i >> 1;                         // smem row 0..63
            int f0 = (i & 1) * 8;                    // float4 half: 0 or 8
            int ktok = tok0 + c * 64 - WIN + r;      // chunk c covers keys [c*64-128, c*64-64)
            const float4* sk = (const float4*)(qkv + (size_t)ktok * QKVD + DIMN + h * DHEAD);
            const float4* sv = (const float4*)(qkv + (size_t)ktok * QKVD + 2 * DIMN + h * DHEAD);
            float4* dK = (float4*)&sK[r][0];
            float4* dV = (float4*)&sV[r][0];
#pragma unroll
            for (int f = 0; f < 8; ++f) { dK[f0 + f] = sk[f0 + f]; dV[f0 + f] = sv[f0 + f]; }
        }
        __syncthreads();

        int jmax;
        if (c < 2) {
            jmax = 64;                               // prev window: all valid (w>0)
        } else {
            jmax = i - (c - 2) * 64 + 1;             // current window: key pos <= i
            jmax = jmax < 0 ? 0 : (jmax > 64 ? 64 : jmax);
        }
        for (int j = 0; j < jmax; ++j) {
            const float4* kr = (const float4*)&sK[j][0];
            float s0 = 0.f, s1 = 0.f, s2 = 0.f, s3 = 0.f;
#pragma unroll
            for (int d4 = 0; d4 < 16; ++d4) {
                float4 kv = kr[d4];
                s0 += q[d4 * 4 + 0] * kv.x;
                s1 += q[d4 * 4 + 1] * kv.y;
                s2 += q[d4 * 4 + 2] * kv.z;
                s3 += q[d4 * 4 + 3] * kv.w;
            }
            float sc = ((s0 + s1) + (s2 + s3)) * 8.0f;   // QK_SCALE
            float mn = fmaxf(m, sc);
            float resc = __expf(m - mn);
            float p    = __expf(sc - mn);
            l = l * resc + p;
            m = mn;
            const float4* vr = (const float4*)&sV[j][0];
#pragma unroll
            for (int d4 = 0; d4 < 16; ++d4) {
                float4 vv = vr[d4];
                acc[d4 * 4 + 0] = acc[d4 * 4 + 0] * resc + p * vv.x;
                acc[d4 * 4 + 1] = acc[d4 * 4 + 1] * resc + p * vv.y;
                acc[d4 * 4 + 2] = acc[d4 * 4 + 2] * resc + p * vv.z;
                acc[d4 * 4 + 3] = acc[d4 * 4 + 3] * resc + p * vv.w;
            }
        }
    }

    float invl = 1.0f / l;
    float* dst = attn_out + (size_t)tok * DIMN + h * DHEAD;
#pragma unroll
    for (int d4 = 0; d4 < 16; ++d4) {
        float4 o4 = make_float4(acc[d4 * 4 + 0] * invl, acc[d4 * 4 + 1] * invl,
                                acc[d4 * 4 + 2] * invl, acc[d4 * 4 + 3] * invl);
        ((float4*)dst)[d4] = o4;
    }
}

// -------- SGEMM-NT: C[M,N] = A[M,K] * B[N,K]^T (+epilogue). 128x128x8, 256 thr --
__device__ __forceinline__ float gelu_f(float x)
{
    return 0.5f * x * (1.0f + erff(x * 0.7071067811865476f));
}

template <int EPI>   // 0 none | 1 +bias[n]+resid | 2 gelu | 3 +resid
__global__ __launch_bounds__(256) void sgemm_nt(const float* __restrict__ A,
                                                const float* __restrict__ B,
                                                float* __restrict__ C,
                                                int M, int N, int K,
                                                const float* __restrict__ bias,
                                                const float* __restrict__ resid)
{
    __shared__ float As[8][128];
    __shared__ float Bs[8][128];
    int bm = blockIdx.y * 128;
    int bn = blockIdx.x * 128;
    int tid  = threadIdx.x;
    int lrow = tid >> 1;
    int lcol = (tid & 1) << 2;
    int ty = tid >> 4, tx = tid & 15;

    const float* Ag = A + (size_t)(bm + lrow) * K + lcol;
    const float* Bg = B + (size_t)(bn + lrow) * K + lcol;

    float acc[8][8];
#pragma unroll
    for (int i = 0; i < 8; ++i)
#pragma unroll
        for (int j = 0; j < 8; ++j) acc[i][j] = 0.f;

    for (int k0 = 0; k0 < K; k0 += 8) {
        float4 a4 = *(const float4*)(Ag + k0);
        float4 b4 = *(const float4*)(Bg + k0);
        As[lcol + 0][lrow] = a4.x; As[lcol + 1][lrow] = a4.y;
        As[lcol + 2][lrow] = a4.z; As[lcol + 3][lrow] = a4.w;
        Bs[lcol + 0][lrow] = b4.x; Bs[lcol + 1][lrow] = b4.y;
        Bs[lcol + 2][lrow] = b4.z; Bs[lcol + 3][lrow] = b4.w;
        __syncthreads();
#pragma unroll
        for (int kk = 0; kk < 8; ++kk) {
            float ar[8], br[8];
            *(float4*)&ar[0] = *(const float4*)&As[kk][ty * 8];
            *(float4*)&ar[4] = *(const float4*)&As[kk][ty * 8 + 4];
            *(float4*)&br[0] = *(const float4*)&Bs[kk][tx * 8];
            *(float4*)&br[4] = *(const float4*)&Bs[kk][tx * 8 + 4];
#pragma unroll
            for (int i = 0; i < 8; ++i)
#pragma unroll
                for (int j = 0; j < 8; ++j) acc[i][j] += ar[i] * br[j];
        }
        __syncthreads();
    }

#pragma unroll
    for (int i = 0; i < 8; ++i) {
        int mrow = bm + ty * 8 + i;
#pragma unroll
        for (int j = 0; j < 8; ++j) {
            int ncol = bn + tx * 8 + j;
            size_t idx = (size_t)mrow * N + ncol;
            float v = acc[i][j];
            if (EPI == 1)      v += bias[ncol] + resid[idx];
            else if (EPI == 2) v = gelu_f(v);
            else if (EPI == 3) v += resid[idx];
            C[idx] = v;
        }
    }
}

// ------------------------------- launch ---------------------------------------
extern "C" void kernel_launch(void* const* d_in, const int* in_sizes, int n_in,
                              void* d_out, int out_size)
{
    const float* x       = (const float*)d_in[0];
    const float* w_qkv   = (const float*)d_in[1];
    const float* q_scale = (const float*)d_in[2];
    const float* k_scale = (const float*)d_in[3];
    const float* w_out   = (const float*)d_in[4];
    const float* b_out   = (const float*)d_in[5];
    const float* ln1_g   = (const float*)d_in[6];
    const float* ln1_b   = (const float*)d_in[7];
    const float* ff_ln_g = (const float*)d_in[8];
    const float* ff_ln_b = (const float*)d_in[9];
    const float* w_ff1   = (const float*)d_in[10];
    const float* w_ff2   = (const float*)d_in[11];
    float* out = (float*)d_out;

    float *p_h, *p_qkv, *p_attn, *p_x1, *p_ff1;
    cudaGetSymbolAddress((void**)&p_h, g_h);
    cudaGetSymbolAddress((void**)&p_qkv, g_qkv);
    cudaGetSymbolAddress((void**)&p_attn, g_attn);
    cudaGetSymbolAddress((void**)&p_x1, g_x1);
    cudaGetSymbolAddress((void**)&p_ff1, g_ff1);

    // 1) h = LN1(x)
    ln_kernel<<<NTOK, 128>>>(x, ln1_g, ln1_b, p_h);

    // 2) qkv = h @ w_qkv^T
    sgemm_nt<0><<<dim3(QKVD / 128, NTOK / 128), 256>>>(p_h, w_qkv, p_qkv,
                                                       NTOK, QKVD, DIMN, nullptr, nullptr);

    // 3) l2norm*scale + rotary for q,k (in place)
    qkpost_kernel<<<NTOK, 256>>>(p_qkv, q_scale, k_scale);

    // 4) local window attention
    attn_kernel<<<dim3(NW, HEADS, BATCH), 128>>>(p_qkv, p_attn);

    // 5) x1 = x + attn @ w_out^T + b_out
    sgemm_nt<1><<<dim3(DIMN / 128, NTOK / 128), 256>>>(p_attn, w_out, p_x1,
                                                       NTOK, DIMN, DIMN, b_out, x);

    // 6) h = LN2(x1)
    ln_kernel<<<NTOK, 128>>>(p_x1, ff_ln_g, ff_ln_b, p_h);

    // 7) ff1 = gelu(h @ w_ff1^T)
    sgemm_nt<2><<<dim3(FFD / 128, NTOK / 128), 256>>>(p_h, w_ff1, p_ff1,
                                                      NTOK, FFD, DIMN, nullptr, nullptr);

    // 8) out = x1 + ff1 @ w_ff2^T
    sgemm_nt<3><<<dim3(DIMN / 128, NTOK / 128), 256>>>(p_ff1, w_ff2, out,
                                                       NTOK, DIMN, FFD, nullptr, p_x1);
}

// round 5
// speedup vs baseline: 2.2580x; 2.2580x over previous
#include <cuda_runtime.h>
#include <cuda_bf16.h>
#include <stdint.h>
#include <math.h>

#define BATCH   8
#define SEQ     4096
#define DIMN    512
#define HEADS   8
#define DHEAD   64
#define WIN     128
#define NW      (SEQ / WIN)
#define NTOK    (BATCH * SEQ)
#define QKVD    (3 * DIMN)
#define FFD     (4 * DIMN)

// ======================= scratch (static device memory) ========================
__device__ float         g_qkv [(size_t)NTOK * QKVD];
__device__ float         g_x1  [(size_t)NTOK * DIMN];
__device__ __nv_bfloat16 g_h_hi [(size_t)NTOK * DIMN];
__device__ __nv_bfloat16 g_h_lo [(size_t)NTOK * DIMN];
__device__ __nv_bfloat16 g_at_hi[(size_t)NTOK * DIMN];
__device__ __nv_bfloat16 g_at_lo[(size_t)NTOK * DIMN];
__device__ __nv_bfloat16 g_f1_hi[(size_t)NTOK * FFD];
__device__ __nv_bfloat16 g_f1_lo[(size_t)NTOK * FFD];
__device__ __nv_bfloat16 g_wqkv_hi[QKVD * DIMN], g_wqkv_lo[QKVD * DIMN];
__device__ __nv_bfloat16 g_wout_hi[DIMN * DIMN], g_wout_lo[DIMN * DIMN];
__device__ __nv_bfloat16 g_wff1_hi[FFD * DIMN],  g_wff1_lo[FFD * DIMN];
__device__ __nv_bfloat16 g_wff2_hi[DIMN * FFD],  g_wff2_lo[DIMN * FFD];

// ============================ helpers ==========================================
__device__ __forceinline__ uint32_t smem_u32(const void* p) {
    uint32_t a;
    asm("{ .reg .u64 t; cvta.to.shared.u64 t, %1; cvt.u32.u64 %0, t; }" : "=r"(a) : "l"(p));
    return a;
}
#define SWZ(o) ((o) ^ (((o) >> 3) & 0x70))   // SW128: stagger 16B chunks per row

__device__ __forceinline__ void cp_async16(uint32_t dst, const void* src) {
    asm volatile("cp.async.cg.shared.global [%0], [%1], 16;" :: "r"(dst), "l"(src));
}
__device__ __forceinline__ void cp_commit_wait() {
    asm volatile("cp.async.commit_group;");
    asm volatile("cp.async.wait_group 0;");
}
__device__ __forceinline__ void ldmatrix_x4(uint32_t& r0, uint32_t& r1,
                                            uint32_t& r2, uint32_t& r3, uint32_t a) {
    asm volatile("ldmatrix.sync.aligned.m8n8.x4.shared.b16 {%0,%1,%2,%3}, [%4];"
                 : "=r"(r0), "=r"(r1), "=r"(r2), "=r"(r3) : "r"(a));
}
__device__ __forceinline__ void mma_bf16(float* c, const uint32_t* a, const uint32_t* b) {
    asm volatile("mma.sync.aligned.m16n8k16.row.col.f32.bf16.bf16.f32 "
                 "{%0,%1,%2,%3}, {%4,%5,%6,%7}, {%8,%9}, {%0,%1,%2,%3};"
                 : "+f"(c[0]), "+f"(c[1]), "+f"(c[2]), "+f"(c[3])
                 : "r"(a[0]), "r"(a[1]), "r"(a[2]), "r"(a[3]), "r"(b[0]), "r"(b[1]));
}
__device__ __forceinline__ void split_bf16(float v, __nv_bfloat16& h, __nv_bfloat16& l) {
    h = __float2bfloat16(v);
    l = __float2bfloat16(v - __bfloat162float(h));
}

// ================= LayerNorm -> bf16 hi/lo split. block = token =================
__global__ __launch_bounds__(128) void ln_kernel(const float* __restrict__ in,
                                                 const float* __restrict__ gamma,
                                                 const float* __restrict__ beta,
                                                 __nv_bfloat16* __restrict__ ohi,
                                                 __nv_bfloat16* __restrict__ olo)
{
    int t = blockIdx.x;
    int tid = threadIdx.x;
    const float4* row = (const float4*)(in + (size_t)t * DIMN);
    float4 v = row[tid];
    float s  = v.x + v.y + v.z + v.w;
    float ss = v.x * v.x + v.y * v.y + v.z * v.z + v.w * v.w;
#pragma unroll
    for (int o = 16; o > 0; o >>= 1) {
        s  += __shfl_xor_sync(0xffffffffu, s, o);
        ss += __shfl_xor_sync(0xffffffffu, ss, o);
    }
    __shared__ float sm[4], sm2[4];
    int w = tid >> 5, lane = tid & 31;
    if (lane == 0) { sm[w] = s; sm2[w] = ss; }
    __syncthreads();
    s  = sm[0] + sm[1] + sm[2] + sm[3];
    ss = sm2[0] + sm2[1] + sm2[2] + sm2[3];
    float mean = s * (1.0f / DIMN);
    float var  = ss * (1.0f / DIMN) - mean * mean;
    float inv  = rsqrtf(var + 1e-5f);
    float4 g = ((const float4*)gamma)[tid];
    float4 b = ((const float4*)beta)[tid];
    float o0 = (v.x - mean) * inv * g.x + b.x;
    float o1 = (v.y - mean) * inv * g.y + b.y;
    float o2 = (v.z - mean) * inv * g.z + b.z;
    float o3 = (v.w - mean) * inv * g.w + b.w;
    __nv_bfloat16 h0, h1, h2, h3, l0, l1, l2, l3;
    split_bf16(o0, h0, l0); split_bf16(o1, h1, l1);
    split_bf16(o2, h2, l2); split_bf16(o3, h3, l3);
    __nv_bfloat162 ph0(h0, h1), ph1(h2, h3), pl0(l0, l1), pl1(l2, l3);
    *(uint2*)(ohi + (size_t)t * DIMN + tid * 4) = make_uint2(*(uint32_t*)&ph0, *(uint32_t*)&ph1);
    *(uint2*)(olo + (size_t)t * DIMN + tid * 4) = make_uint2(*(uint32_t*)&pl0, *(uint32_t*)&pl1);
}

// ================= weight split: fp32 -> bf16 hi/lo =============================
__global__ void split_kernel(const float* __restrict__ in,
                             __nv_bfloat16* __restrict__ hi,
                             __nv_bfloat16* __restrict__ lo, int n4)
{
    int i = blockIdx.x * blockDim.x + threadIdx.x;
    if (i >= n4) return;
    float4 v = ((const float4*)in)[i];
    __nv_bfloat16 h0, h1, h2, h3, l0, l1, l2, l3;
    split_bf16(v.x, h0, l0); split_bf16(v.y, h1, l1);
    split_bf16(v.z, h2, l2); split_bf16(v.w, h3, l3);
    __nv_bfloat162 ph0(h0, h1), ph1(h2, h3), pl0(l0, l1), pl1(l2, l3);
    ((uint2*)hi)[i] = make_uint2(*(uint32_t*)&ph0, *(uint32_t*)&ph1);
    ((uint2*)lo)[i] = make_uint2(*(uint32_t*)&pl0, *(uint32_t*)&pl1);
}

// ========= q/k post: l2norm*scale + rotary (double trig, fp32 phase) ============
__global__ __launch_bounds__(256) void qkpost_kernel(float* __restrict__ qkv,
                                                     const float* __restrict__ qsc,
                                                     const float* __restrict__ ksc)
{
    int t = blockIdx.x;
    int n = t & (SEQ - 1);
    int h = threadIdx.x >> 5;
    int lane = threadIdx.x & 31;

    double invf_d = exp(-(double)(2 * lane) * (9.210340371976184 / 64.0));
    float invf = (float)invf_d;
    float ph = (float)n * invf;
    double sd, cd;
    sincos((double)ph, &sd, &cd);
    float c = (float)cd, s = (float)sd;

    float* base = qkv + (size_t)t * QKVD + h * DHEAD;
    {
        float a = base[lane], b = base[lane + 32];
        float ssq = a * a + b * b;
#pragma unroll
        for (int o = 16; o > 0; o >>= 1) ssq += __shfl_xor_sync(0xffffffffu, ssq, o);
        float inv = 1.0f / fmaxf(sqrtf(ssq), 1e-12f);
        float an = a * inv * qsc[lane];
        float bn = b * inv * qsc[lane + 32];
        base[lane]      = an * c - bn * s;
        base[lane + 32] = bn * c + an * s;
    }
    {
        float* kb = base + DIMN;
        float a = kb[lane], b = kb[lane + 32];
        float ssq = a * a + b * b;
#pragma unroll
        for (int o = 16; o > 0; o >>= 1) ssq += __shfl_xor_sync(0xffffffffu, ssq, o);
        float inv = 1.0f / fmaxf(sqrtf(ssq), 1e-12f);
        float an = a * inv * ksc[lane];
        float bn = b * inv * ksc[lane + 32];
        kb[lane]      = an * c - bn * s;
        kb[lane + 32] = bn * c + an * s;
    }
}

// ====== local-window attention, epilogue -> bf16 hi/lo ==========================
__global__ __launch_bounds__(128) void attn_kernel(const float* __restrict__ qkv,
                                                   __nv_bfloat16* __restrict__ ohi,
                                                   __nv_bfloat16* __restrict__ olo)
{
    __shared__ float sK[64][DHEAD];
    __shared__ float sV[64][DHEAD];

    int w = blockIdx.x, h = blockIdx.y, b = blockIdx.z;
    int i = threadIdx.x;
    int tok0 = b * SEQ + w * WIN;
    int tok  = tok0 + i;

    float q[DHEAD];
    {
        const float4* srcQ = (const float4*)(qkv + (size_t)tok * QKVD + h * DHEAD);
#pragma unroll
        for (int d4 = 0; d4 < 16; ++d4) {
            float4 t4 = srcQ[d4];
            q[d4 * 4 + 0] = t4.x; q[d4 * 4 + 1] = t4.y;
            q[d4 * 4 + 2] = t4.z; q[d4 * 4 + 3] = t4.w;
        }
    }

    float acc[DHEAD];
#pragma unroll
    for (int d = 0; d < DHEAD; ++d) acc[d] = 0.f;
    float m = -1e30f, l = 0.f;

#pragma unroll 1
    for (int c = 0; c < 4; ++c) {
        if (c < 2 && w == 0) continue;

        __syncthreads();
        {
            int r  = i >> 1;
            int f0 = (i & 1) * 8;
            int ktok = tok0 + c * 64 - WIN + r;
            const float4* sk = (const float4*)(qkv + (size_t)ktok * QKVD + DIMN + h * DHEAD);
            const float4* sv = (const float4*)(qkv + (size_t)ktok * QKVD + 2 * DIMN + h * DHEAD);
            float4* dK = (float4*)&sK[r][0];
            float4* dV = (float4*)&sV[r][0];
#pragma unroll
            for (int f = 0; f < 8; ++f) { dK[f0 + f] = sk[f0 + f]; dV[f0 + f] = sv[f0 + f]; }
        }
        __syncthreads();

        int jmax;
        if (c < 2) jmax = 64;
        else {
            jmax = i - (c - 2) * 64 + 1;
            jmax = jmax < 0 ? 0 : (jmax > 64 ? 64 : jmax);
        }
        for (int j = 0; j < jmax; ++j) {
            const float4* kr = (const float4*)&sK[j][0];
            float s0 = 0.f, s1 = 0.f, s2 = 0.f, s3 = 0.f;
#pragma unroll
            for (int d4 = 0; d4 < 16; ++d4) {
                float4 kv = kr[d4];
                s0 += q[d4 * 4 + 0] * kv.x;
                s1 += q[d4 * 4 + 1] * kv.y;
                s2 += q[d4 * 4 + 2] * kv.z;
                s3 += q[d4 * 4 + 3] * kv.w;
            }
            float sc = ((s0 + s1) + (s2 + s3)) * 8.0f;
            float mn = fmaxf(m, sc);
            float resc = __expf(m - mn);
            float p    = __expf(sc - mn);
            l = l * resc + p;
            m = mn;
            const float4* vr = (const float4*)&sV[j][0];
#pragma unroll
            for (int d4 = 0; d4 < 16; ++d4) {
                float4 vv = vr[d4];
                acc[d4 * 4 + 0] = acc[d4 * 4 + 0] * resc + p * vv.x;
                acc[d4 * 4 + 1] = acc[d4 * 4 + 1] * resc + p * vv.y;
                acc[d4 * 4 + 2] = acc[d4 * 4 + 2] * resc + p * vv.z;
                acc[d4 * 4 + 3] = acc[d4 * 4 + 3] * resc + p * vv.w;
            }
        }
    }

    float invl = 1.0f / l;
    size_t dstoff = (size_t)tok * DIMN + h * DHEAD;
#pragma unroll
    for (int d4 = 0; d4 < 16; ++d4) {
        float v0 = acc[d4 * 4 + 0] * invl, v1 = acc[d4 * 4 + 1] * invl;
        float v2 = acc[d4 * 4 + 2] * invl, v3 = acc[d4 * 4 + 3] * invl;
        __nv_bfloat16 h0, h1, h2, h3, l0, l1, l2, l3;
        split_bf16(v0, h0, l0); split_bf16(v1, h1, l1);
        split_bf16(v2, h2, l2); split_bf16(v3, h3, l3);
        __nv_bfloat162 ph0(h0, h1), ph1(h2, h3), pl0(l0, l1), pl1(l2, l3);
        *(uint2*)(ohi + dstoff + d4 * 4) = make_uint2(*(uint32_t*)&ph0, *(uint32_t*)&ph1);
        *(uint2*)(olo + dstoff + d4 * 4) = make_uint2(*(uint32_t*)&pl0, *(uint32_t*)&pl1);
    }
}

// ============== HMMA GEMM, bf16x3 split, 128x128 tile, mma.sync =================
// C[M,N] = A[M,K] @ B[N,K]^T in virtual fp32: Ahi*Bhi + Alo*Bhi + Ahi*Blo.
// 256 threads = 8 warps: warpM = wid&3 (32 rows each), warpN = wid>>2 (64 cols).
// smem: 4 tiles (Ahi, Alo, Bhi, Blo) of 128 rows x 64 bf16 (128B rows, SW128).
// EPI: 0 fp32 | 1 +bias+resid fp32 | 2 gelu -> bf16 hi/lo | 3 +resid fp32
#define KBLK     64
#define TILE_B   16384
#define SM_TOTAL (4 * TILE_B)

__device__ __forceinline__ float gelu_f(float x)
{
    return 0.5f * x * (1.0f + erff(x * 0.7071067811865476f));
}

template <int EPI>
__global__ __launch_bounds__(256, 2) void gemm_tc(
    const __nv_bfloat16* __restrict__ Ahi, const __nv_bfloat16* __restrict__ Alo,
    const __nv_bfloat16* __restrict__ Bhi, const __nv_bfloat16* __restrict__ Blo,
    int M, int N, int K,
    float* __restrict__ Cf,
    __nv_bfloat16* __restrict__ Chi, __nv_bfloat16* __restrict__ Clo,
    const float* __restrict__ bias, const float* __restrict__ resid)
{
    extern __shared__ char smem[];
    uint32_t sb = smem_u32(smem);
    int tid = threadIdx.x, wid = tid >> 5, lane = tid & 31;
    int warpM = wid & 3, warpN = wid >> 2;
    int bm = blockIdx.y * 128, bn = blockIdx.x * 128;

    float acc[2][8][4];
#pragma unroll
    for (int mi = 0; mi < 2; ++mi)
#pragma unroll
        for (int ni = 0; ni < 8; ++ni)
#pragma unroll
            for (int r = 0; r < 4; ++r) acc[mi][ni][r] = 0.f;

    // ldmatrix lane->address mapping (element coords within tile)
    int aRow  = lane & 15;              // + warpM*32 + mi*16
    int aKoff = (lane >> 4) << 3;       // + k16*16
    int bRow  = (lane & 7) + ((lane >> 4) << 3);   // + warpN*64 + np*16
    int bKoff = ((lane >> 3) & 1) << 3;

    int kchunks = K / KBLK;
#pragma unroll 1
    for (int kc = 0; kc < kchunks; ++kc) {
        int k0 = kc * KBLK;
        __syncthreads();
        // fill 4 tiles via cp.async (each thread: 16 x 16B)
#pragma unroll
        for (int tile = 0; tile < 4; ++tile) {
            const __nv_bfloat16* src = (tile == 0) ? Ahi : (tile == 1) ? Alo
                                      : (tile == 2) ? Bhi : Blo;
            int rbase = (tile < 2) ? bm : bn;
            uint32_t dstb = sb + tile * TILE_B;
#pragma unroll
            for (int it = 0; it < 4; ++it) {
                int idx = tid + it * 256;          // 0..1023
                int row = idx >> 3, c16 = idx & 7;
                cp_async16(dstb + SWZ(row * 128 + c16 * 16),
                           src + (size_t)(rbase + row) * K + k0 + c16 * 8);
            }
        }
        cp_commit_wait();
        __syncthreads();

#pragma unroll 1
        for (int k16 = 0; k16 < KBLK / 16; ++k16) {
#pragma unroll 1
            for (int term = 0; term < 3; ++term) {
                uint32_t aBase = sb + (term == 1 ? TILE_B : 0);
                uint32_t bBase = sb + 2 * TILE_B + (term == 2 ? TILE_B : 0);
                uint32_t a[2][4], b[8][2];
#pragma unroll
                for (int mi = 0; mi < 2; ++mi) {
                    uint32_t addr = aBase + SWZ((warpM * 32 + mi * 16 + aRow) * 128 +
                                                (k16 * 16 + aKoff) * 2);
                    ldmatrix_x4(a[mi][0], a[mi][1], a[mi][2], a[mi][3], addr);
                }
#pragma unroll
                for (int np = 0; np < 4; ++np) {
                    uint32_t addr = bBase + SWZ((warpN * 64 + np * 16 + bRow) * 128 +
                                                (k16 * 16 + bKoff) * 2);
                    ldmatrix_x4(b[np * 2][0], b[np * 2][1],
                                b[np * 2 + 1][0], b[np * 2 + 1][1], addr);
                }
#pragma unroll
                for (int mi = 0; mi < 2; ++mi)
#pragma unroll
                    for (int ni = 0; ni < 8; ++ni)
                        mma_bf16(acc[mi][ni], a[mi], b[ni]);
            }
        }
    }

    // epilogue: c0,c1 -> (row, col..col+1); c2,c3 -> (row+8, ...)
#pragma unroll
    for (int mi = 0; mi < 2; ++mi)
#pragma unroll
        for (int ni = 0; ni < 8; ++ni) {
            int row = bm + warpM * 32 + mi * 16 + (lane >> 2);
            int col = bn + warpN * 64 + ni * 8 + (lane & 3) * 2;
#pragma unroll
            for (int hh = 0; hh < 2; ++hh) {
                int r = row + hh * 8;
                float v0 = acc[mi][ni][hh * 2 + 0];
                float v1 = acc[mi][ni][hh * 2 + 1];
                size_t idx = (size_t)r * N + col;
                if (EPI == 2) {
                    v0 = gelu_f(v0); v1 = gelu_f(v1);
                    __nv_bfloat16 h0, h1, l0, l1;
                    split_bf16(v0, h0, l0); split_bf16(v1, h1, l1);
                    __nv_bfloat162 hp(h0, h1), lp(l0, l1);
                    *(uint32_t*)(Chi + idx) = *(uint32_t*)&hp;
                    *(uint32_t*)(Clo + idx) = *(uint32_t*)&lp;
                } else {
                    if (EPI == 1) {
                        float2 rs = *(const float2*)(resid + idx);
                        v0 += bias[col] + rs.x;
                        v1 += bias[col + 1] + rs.y;
                    } else if (EPI == 3) {
                        float2 rs = *(const float2*)(resid + idx);
                        v0 += rs.x; v1 += rs.y;
                    }
                    *(float2*)(Cf + idx) = make_float2(v0, v1);
                }
            }
        }
}

// ------------------------------- launch ---------------------------------------
extern "C" void kernel_launch(void* const* d_in, const int* in_sizes, int n_in,
                              void* d_out, int out_size)
{
    const float* x       = (const float*)d_in[0];
    const float* w_qkv   = (const float*)d_in[1];
    const float* q_scale = (const float*)d_in[2];
    const float* k_scale = (const float*)d_in[3];
    const float* w_out   = (const float*)d_in[4];
    const float* b_out   = (const float*)d_in[5];
    const float* ln1_g   = (const float*)d_in[6];
    const float* ln1_b   = (const float*)d_in[7];
    const float* ff_ln_g = (const float*)d_in[8];
    const float* ff_ln_b = (const float*)d_in[9];
    const float* w_ff1   = (const float*)d_in[10];
    const float* w_ff2   = (const float*)d_in[11];
    float* out = (float*)d_out;

    float *p_qkv, *p_x1;
    __nv_bfloat16 *p_h_hi, *p_h_lo, *p_at_hi, *p_at_lo, *p_f1_hi, *p_f1_lo;
    __nv_bfloat16 *p_wqkv_hi, *p_wqkv_lo, *p_wout_hi, *p_wout_lo;
    __nv_bfloat16 *p_wff1_hi, *p_wff1_lo, *p_wff2_hi, *p_wff2_lo;
    cudaGetSymbolAddress((void**)&p_qkv, g_qkv);
    cudaGetSymbolAddress((void**)&p_x1, g_x1);
    cudaGetSymbolAddress((void**)&p_h_hi, g_h_hi);
    cudaGetSymbolAddress((void**)&p_h_lo, g_h_lo);
    cudaGetSymbolAddress((void**)&p_at_hi, g_at_hi);
    cudaGetSymbolAddress((void**)&p_at_lo, g_at_lo);
    cudaGetSymbolAddress((void**)&p_f1_hi, g_f1_hi);
    cudaGetSymbolAddress((void**)&p_f1_lo, g_f1_lo);
    cudaGetSymbolAddress((void**)&p_wqkv_hi, g_wqkv_hi);
    cudaGetSymbolAddress((void**)&p_wqkv_lo, g_wqkv_lo);
    cudaGetSymbolAddress((void**)&p_wout_hi, g_wout_hi);
    cudaGetSymbolAddress((void**)&p_wout_lo, g_wout_lo);
    cudaGetSymbolAddress((void**)&p_wff1_hi, g_wff1_hi);
    cudaGetSymbolAddress((void**)&p_wff1_lo, g_wff1_lo);
    cudaGetSymbolAddress((void**)&p_wff2_hi, g_wff2_hi);
    cudaGetSymbolAddress((void**)&p_wff2_lo, g_wff2_lo);

    cudaFuncSetAttribute(gemm_tc<0>, cudaFuncAttributeMaxDynamicSharedMemorySize, SM_TOTAL);
    cudaFuncSetAttribute(gemm_tc<1>, cudaFuncAttributeMaxDynamicSharedMemorySize, SM_TOTAL);
    cudaFuncSetAttribute(gemm_tc<2>, cudaFuncAttributeMaxDynamicSharedMemorySize, SM_TOTAL);
    cudaFuncSetAttribute(gemm_tc<3>, cudaFuncAttributeMaxDynamicSharedMemorySize, SM_TOTAL);

    // weight splits
    split_kernel<<<(QKVD * DIMN / 4 + 255) / 256, 256>>>(w_qkv, p_wqkv_hi, p_wqkv_lo, QKVD * DIMN / 4);
    split_kernel<<<(DIMN * DIMN / 4 + 255) / 256, 256>>>(w_out, p_wout_hi, p_wout_lo, DIMN * DIMN / 4);
    split_kernel<<<(FFD * DIMN / 4 + 255) / 256, 256>>>(w_ff1, p_wff1_hi, p_wff1_lo, FFD * DIMN / 4);
    split_kernel<<<(DIMN * FFD / 4 + 255) / 256, 256>>>(w_ff2, p_wff2_hi, p_wff2_lo, DIMN * FFD / 4);

    // 1) h = LN1(x) -> hi/lo
    ln_kernel<<<NTOK, 128>>>(x, ln1_g, ln1_b, p_h_hi, p_h_lo);

    // 2) qkv = h @ w_qkv^T (fp32 out)
    gemm_tc<0><<<dim3(QKVD / 128, NTOK / 128), 256, SM_TOTAL>>>(
        p_h_hi, p_h_lo, p_wqkv_hi, p_wqkv_lo, NTOK, QKVD, DIMN,
        p_qkv, nullptr, nullptr, nullptr, nullptr);

    // 3) l2norm*scale + rotary (in place)
    qkpost_kernel<<<NTOK, 256>>>(p_qkv, q_scale, k_scale);

    // 4) attention -> hi/lo
    attn_kernel<<<dim3(NW, HEADS, BATCH), 128>>>(p_qkv, p_at_hi, p_at_lo);

    // 5) x1 = x + attn @ w_out^T + b_out
    gemm_tc<1><<<dim3(DIMN / 128, NTOK / 128), 256, SM_TOTAL>>>(
        p_at_hi, p_at_lo, p_wout_hi, p_wout_lo, NTOK, DIMN, DIMN,
        p_x1, nullptr, nullptr, b_out, x);

    // 6) h = LN2(x1) -> hi/lo
    ln_kernel<<<NTOK, 128>>>(p_x1, ff_ln_g, ff_ln_b, p_h_hi, p_h_lo);

    // 7) ff1 = gelu(h @ w_ff1^T) -> hi/lo
    gemm_tc<2><<<dim3(FFD / 128, NTOK / 128), 256, SM_TOTAL>>>(
        p_h_hi, p_h_lo, p_wff1_hi, p_wff1_lo, NTOK, FFD, DIMN,
        nullptr, p_f1_hi, p_f1_lo, nullptr, nullptr);

    // 8) out = x1 + ff1 @ w_ff2^T
    gemm_tc<3><<<dim3(DIMN / 128, NTOK / 128), 256, SM_TOTAL>>>(
        p_f1_hi, p_f1_lo, p_wff2_hi, p_wff2_lo, NTOK, DIMN, FFD,
        out, nullptr, nullptr, nullptr, p_x1);
}